// round 7
// baseline (speedup 1.0000x reference)
#include <cuda_runtime.h>
#include <cuda_bf16.h>
#include <math.h>

// ----------------------------------------------------------------------------
// GraphSAGE (3 layers) + up-proj + FUSED tri-pooling + MLP head.
// CSR gather, paired-node shuffle GEMMs, no h4 materialization.
// N=100000, E=1600000, G=256, H=32, UP=128, out 51.
// Replay-safe: g_cnt/g_gsum/g_gmax are zeroed by k_head's tail each run
// (and statically zero for the very first call).
// ----------------------------------------------------------------------------

#define MAXN 100000
#define MAXE 1600000
#define MAXG 256

__device__ int      g_csr[MAXE];
__device__ int      g_cnt[MAXN];          // in-degree histogram (pre-zeroed)
__device__ int      g_rowptr[MAXN + 1];
__device__ int      g_cursor[MAXN];
__device__ float    g_h1[MAXN * 32];
__device__ float    g_h2[MAXN * 32];
__device__ int      g_start[MAXG + 1];
__device__ float    g_gsum[MAXG * 128];   // per-graph channel sums (pre-zeroed)
__device__ unsigned g_gmax[MAXG * 128];   // encoded per-graph maxima (pre-zeroed)

__device__ __forceinline__ float lrelu(float v) { return v > 0.f ? v : 0.01f * v; }

// Order-preserving float->uint encoding for atomicMax.
__device__ __forceinline__ unsigned fenc(float f) {
    unsigned b = __float_as_uint(f);
    return (b & 0x80000000u) ? ~b : (b | 0x80000000u);
}
__device__ __forceinline__ float fdec(unsigned u) {
    return (u & 0x80000000u) ? __uint_as_float(u & 0x7FFFFFFFu)
                             : __uint_as_float(~u);
}

// Per-block dtype sniff: int64 little-endian small nonneg => odd words zero.
// Reads 64 words starting at `base` (must be even, in-bounds).
__device__ __forceinline__ int sniff64(const unsigned* w, int base) {
    int lane = threadIdx.x & 31;
    unsigned v = w[base + 2 * lane + 1];
    unsigned nz = __ballot_sync(0xffffffffu, v != 0u);
    return nz == 0u;
}

// ---------------------------------------------------------------------------
// 1) In-degree histogram (g_cnt pre-zeroed).
// ---------------------------------------------------------------------------
__global__ void k_hist(const void* __restrict__ eidx, int E) {
    __shared__ int se64;
    if (threadIdx.x < 32) {
        int f = sniff64((const unsigned*)eidx, 0);
        if (threadIdx.x == 0) se64 = f;
    }
    __syncthreads();
    int i = blockIdx.x * blockDim.x + threadIdx.x;
    if (i >= E) return;
    int d = se64 ? (int)((const long long*)eidx)[(size_t)E + i]
                 : ((const int*)eidx)[E + i];
    atomicAdd(&g_cnt[d], 1);
}

// ---------------------------------------------------------------------------
// 2) Single-block chunked exclusive scan: g_cnt -> g_rowptr (+cursor).
// ---------------------------------------------------------------------------
__global__ void k_scan1b(int N, int E) {
    __shared__ int ssum[1024];
    int t = threadIdx.x;
    int chunk = (N + 1023) / 1024;
    int a = t * chunk;
    int b = min(N, a + chunk);
    int s = 0;
    for (int i = a; i < b; i++) s += g_cnt[i];
    ssum[t] = s;
    __syncthreads();
    for (int off = 1; off < 1024; off <<= 1) {
        int u = (t >= off) ? ssum[t - off] : 0;
        __syncthreads();
        ssum[t] += u;
        __syncthreads();
    }
    int run = ssum[t] - s;
    for (int i = a; i < b; i++) {
        g_rowptr[i] = run;
        g_cursor[i] = run;
        run += g_cnt[i];
    }
    if (t == 1023) g_rowptr[N] = E;
}

// ---------------------------------------------------------------------------
// 3) CSR fill straight from the input edge index.
// ---------------------------------------------------------------------------
__global__ void k_csrfill(const void* __restrict__ eidx, int E) {
    __shared__ int se64;
    if (threadIdx.x < 32) {
        int f = sniff64((const unsigned*)eidx, 0);
        if (threadIdx.x == 0) se64 = f;
    }
    __syncthreads();
    int i = blockIdx.x * blockDim.x + threadIdx.x;
    if (i >= E) return;
    int s, d;
    if (se64) {
        const long long* p = (const long long*)eidx;
        s = (int)p[i];
        d = (int)p[(size_t)E + i];
    } else {
        const int* p = (const int*)eidx;
        s = p[i];
        d = p[E + i];
    }
    int pos = atomicAdd(&g_cursor[d], 1);
    g_csr[pos] = s;
}

// ---------------------------------------------------------------------------
// Warp-cooperative 32-channel gather-sum over CSR edges (proven body).
// ---------------------------------------------------------------------------
__device__ __forceinline__ float gather32(const float* __restrict__ h,
                                          int s0, int s1, int lane) {
    float a0 = 0.f, a1 = 0.f, a2 = 0.f, a3 = 0.f;
    for (int base = s0; base < s1; base += 32) {
        int e = base + lane;
        int sidx = (e < s1) ? __ldg(&g_csr[e]) : 0;
        int cnt = min(32, s1 - base);
        int k = 0;
        for (; k + 4 <= cnt; k += 4) {
            int i0 = __shfl_sync(0xffffffffu, sidx, k);
            int i1 = __shfl_sync(0xffffffffu, sidx, k + 1);
            int i2 = __shfl_sync(0xffffffffu, sidx, k + 2);
            int i3 = __shfl_sync(0xffffffffu, sidx, k + 3);
            a0 += __ldg(&h[i0 * 32 + lane]);
            a1 += __ldg(&h[i1 * 32 + lane]);
            a2 += __ldg(&h[i2 * 32 + lane]);
            a3 += __ldg(&h[i3 * 32 + lane]);
        }
        for (; k < cnt; k++) {
            int ik = __shfl_sync(0xffffffffu, sidx, k);
            a0 += __ldg(&h[ik * 32 + lane]);
        }
    }
    return (a0 + a1) + (a2 + a3);
}

// ---------------------------------------------------------------------------
// 4) Layer 1: warp per node, scalar gather of x + 32-wide transform.
// ---------------------------------------------------------------------------
__global__ void k_l1(const float* __restrict__ x, const float* __restrict__ W1l,
                     const float* __restrict__ b1, const float* __restrict__ W1r,
                     int N) {
    int lane = threadIdx.x & 31;
    int node = (blockIdx.x * blockDim.x + threadIdx.x) >> 5;
    if (node >= N) return;
    int s0 = g_rowptr[node], s1 = g_rowptr[node + 1];
    float a = 0.f;
    for (int j = s0 + lane; j < s1; j += 32) a += __ldg(&x[__ldg(&g_csr[j])]);
    #pragma unroll
    for (int off = 16; off; off >>= 1) a += __shfl_xor_sync(0xffffffffu, a, off);
    float xv = __ldg(&x[node]);
    g_h1[node * 32 + lane] =
        lrelu(a * __ldg(&W1l[lane]) + xv * __ldg(&W1r[lane]) + __ldg(&b1[lane]));
}

// ---------------------------------------------------------------------------
// 5) Layer 2: warp per NODE PAIR. Shared weight-LDS, dual FFMA chains.
// ---------------------------------------------------------------------------
__global__ __launch_bounds__(256, 4)
void k_sage2(const float* __restrict__ Wl, const float* __restrict__ b,
             const float* __restrict__ Wr, int N) {
    __shared__ float sWl[1024], sWr[1024], sb[32];
    for (int i = threadIdx.x; i < 1024; i += blockDim.x) { sWl[i] = Wl[i]; sWr[i] = Wr[i]; }
    if (threadIdx.x < 32) sb[threadIdx.x] = b[threadIdx.x];
    __syncthreads();
    int lane = threadIdx.x & 31;
    int pair = (blockIdx.x * blockDim.x + threadIdx.x) >> 5;
    int nA = pair * 2;
    if (nA >= N) return;
    int nB = nA + 1;
    bool vB = (nB < N);
    int nBc = vB ? nB : nA;

    int a0 = g_rowptr[nA], a1 = g_rowptr[nA + 1];
    int b0 = g_rowptr[nBc], b1r = g_rowptr[nBc + 1];
    float aggA = gather32(g_h1, a0, a1, lane);
    float aggB = gather32(g_h1, b0, b1r, lane);
    float hvA = g_h1[nA * 32 + lane];
    float hvB = g_h1[nBc * 32 + lane];

    float accA = sb[lane], accB = sb[lane];
    #pragma unroll
    for (int k = 0; k < 32; k++) {
        float wl = sWl[k * 32 + lane];
        float wr = sWr[k * 32 + lane];
        accA += __shfl_sync(0xffffffffu, aggA, k) * wl
              + __shfl_sync(0xffffffffu, hvA, k)  * wr;
        accB += __shfl_sync(0xffffffffu, aggB, k) * wl
              + __shfl_sync(0xffffffffu, hvB, k)  * wr;
    }
    g_h2[nA * 32 + lane] = lrelu(accA);
    if (vB) g_h2[nB * 32 + lane] = lrelu(accB);
}

// ---------------------------------------------------------------------------
// 6) Layer 3 (mean) + up-proj + FUSED pooling.
// Block = 256 contiguous nodes; warp w owns strip [base+32w, base+32w+32).
// Warp accumulates float4 sum/max in registers, flushes to global atomics
// only on graph boundary (sorted batch => ~1 boundary per warp).
// ---------------------------------------------------------------------------
__device__ __forceinline__ void flush_pool(int g, int lane, float4 ps, float4 pm) {
    if (g < 0) return;
    float* sp = g_gsum + g * 128 + lane * 4;
    unsigned* mp = g_gmax + g * 128 + lane * 4;
    atomicAdd(sp + 0, ps.x); atomicAdd(sp + 1, ps.y);
    atomicAdd(sp + 2, ps.z); atomicAdd(sp + 3, ps.w);
    atomicMax(mp + 0, fenc(pm.x)); atomicMax(mp + 1, fenc(pm.y));
    atomicMax(mp + 2, fenc(pm.z)); atomicMax(mp + 3, fenc(pm.w));
}

__global__ __launch_bounds__(256, 3)
void k_sage3up_pool(const float* __restrict__ W3l, const float* __restrict__ b3,
                    const float* __restrict__ W3r, const float* __restrict__ Wu,
                    const float* __restrict__ bu, const void* __restrict__ batch,
                    int N, int bbase) {
    __shared__ float sWl[1024], sWr[1024], sWu[4096], sb[32], sbu[128];
    __shared__ int sb64;
    for (int i = threadIdx.x; i < 1024; i += blockDim.x) { sWl[i] = W3l[i]; sWr[i] = W3r[i]; }
    for (int i = threadIdx.x; i < 4096; i += blockDim.x) sWu[i] = Wu[i];
    if (threadIdx.x < 32) {
        sb[threadIdx.x] = b3[threadIdx.x];
        int f = sniff64((const unsigned*)batch, bbase);
        if (threadIdx.x == 0) sb64 = f;
    }
    if (threadIdx.x < 128) sbu[threadIdx.x] = bu[threadIdx.x];
    __syncthreads();

    int lane = threadIdx.x & 31;
    int w = threadIdx.x >> 5;
    int base = blockIdx.x * 256 + w * 32;
    int e64 = sb64;

    int gcur = -1;
    float4 psum = make_float4(0.f, 0.f, 0.f, 0.f);
    float4 pmax = make_float4(-INFINITY, -INFINITY, -INFINITY, -INFINITY);

    for (int i = 0; i < 32; i += 2) {
        int nA = base + i;
        if (nA >= N) break;
        int nB = nA + 1;
        bool vB = (nB < N);
        int nBc = vB ? nB : nA;

        int a0 = g_rowptr[nA], a1 = g_rowptr[nA + 1];
        int b0 = g_rowptr[nBc], b1r = g_rowptr[nBc + 1];
        float aggA = gather32(g_h2, a0, a1, lane);
        float aggB = gather32(g_h2, b0, b1r, lane);
        aggA *= 1.0f / fmaxf((float)(a1 - a0), 1.0f);
        aggB *= 1.0f / fmaxf((float)(b1r - b0), 1.0f);
        float hvA = g_h2[nA * 32 + lane];
        float hvB = g_h2[nBc * 32 + lane];

        float accA = sb[lane], accB = sb[lane];
        #pragma unroll
        for (int k = 0; k < 32; k++) {
            float wl = sWl[k * 32 + lane];
            float wr = sWr[k * 32 + lane];
            accA += __shfl_sync(0xffffffffu, aggA, k) * wl
                  + __shfl_sync(0xffffffffu, hvA, k)  * wr;
            accB += __shfl_sync(0xffffffffu, aggB, k) * wl
                  + __shfl_sync(0xffffffffu, hvB, k)  * wr;
        }
        float h3A = lrelu(accA);
        float h3B = lrelu(accB);

        // Up-proj pair: shared weight LDS128, dual float4 accumulators.
        float4 uA = *(const float4*)(sbu + lane * 4);
        float4 uB = uA;
        #pragma unroll
        for (int k = 0; k < 32; k++) {
            float4 wv = *(const float4*)(sWu + k * 128 + lane * 4);
            float hkA = __shfl_sync(0xffffffffu, h3A, k);
            float hkB = __shfl_sync(0xffffffffu, h3B, k);
            uA.x += hkA * wv.x; uA.y += hkA * wv.y;
            uA.z += hkA * wv.z; uA.w += hkA * wv.w;
            uB.x += hkB * wv.x; uB.y += hkB * wv.y;
            uB.z += hkB * wv.z; uB.w += hkB * wv.w;
        }
        uA.x = lrelu(uA.x); uA.y = lrelu(uA.y); uA.z = lrelu(uA.z); uA.w = lrelu(uA.w);
        uB.x = lrelu(uB.x); uB.y = lrelu(uB.y); uB.z = lrelu(uB.z); uB.w = lrelu(uB.w);

        // Fused pooling: register accumulation, flush on graph boundary.
        int gA = e64 ? (int)((const long long*)batch)[nA] : ((const int*)batch)[nA];
        if (gA != gcur) {
            flush_pool(gcur, lane, psum, pmax);
            gcur = gA;
            psum = make_float4(0.f, 0.f, 0.f, 0.f);
            pmax = make_float4(-INFINITY, -INFINITY, -INFINITY, -INFINITY);
        }
        psum.x += uA.x; psum.y += uA.y; psum.z += uA.z; psum.w += uA.w;
        pmax.x = fmaxf(pmax.x, uA.x); pmax.y = fmaxf(pmax.y, uA.y);
        pmax.z = fmaxf(pmax.z, uA.z); pmax.w = fmaxf(pmax.w, uA.w);

        if (vB) {
            int gB = e64 ? (int)((const long long*)batch)[nB] : ((const int*)batch)[nB];
            if (gB != gcur) {
                flush_pool(gcur, lane, psum, pmax);
                gcur = gB;
                psum = make_float4(0.f, 0.f, 0.f, 0.f);
                pmax = make_float4(-INFINITY, -INFINITY, -INFINITY, -INFINITY);
            }
            psum.x += uB.x; psum.y += uB.y; psum.z += uB.z; psum.w += uB.w;
            pmax.x = fmaxf(pmax.x, uB.x); pmax.y = fmaxf(pmax.y, uB.y);
            pmax.z = fmaxf(pmax.z, uB.z); pmax.w = fmaxf(pmax.w, uB.w);
        }
    }
    flush_pool(gcur, lane, psum, pmax);
}

// ---------------------------------------------------------------------------
// 7) Per-graph start offsets from sorted batch array (for counts).
// ---------------------------------------------------------------------------
__global__ void k_starts(const void* __restrict__ batch, int N, int G, int bbase) {
    __shared__ int sb64;
    if (threadIdx.x < 32) {
        int f = sniff64((const unsigned*)batch, bbase);
        if (threadIdx.x == 0) sb64 = f;
    }
    __syncthreads();
    int i = blockIdx.x * blockDim.x + threadIdx.x;
    if (i >= N) return;
    long long bi, bp;
    if (sb64) {
        const long long* p = (const long long*)batch;
        bi = p[i]; bp = (i == 0) ? -1LL : p[i - 1];
    } else {
        const int* p = (const int*)batch;
        bi = p[i]; bp = (i == 0) ? -1LL : p[i - 1];
    }
    if (bi != bp) for (long long g = bp + 1; g <= bi; g++) g_start[g] = i;
    if (i == N - 1) for (long long g = bi + 1; g <= G; g++) g_start[g] = N;
}

// ---------------------------------------------------------------------------
// 8) Head: z = [mean|max|sum] -> lrelu(@Wf1+bf1) -> @Wf2+bf2.
// Tail re-zeroes g_cnt / own-graph g_gsum,g_gmax for the next replay.
// ---------------------------------------------------------------------------
__global__ void k_head(const float* __restrict__ Wf1, const float* __restrict__ bf1,
                       const float* __restrict__ Wf2, const float* __restrict__ bf2,
                       float* __restrict__ out, int N, int G) {
    __shared__ float sz[384], sz2[128];
    int g = blockIdx.x;
    int c = threadIdx.x;   // 128 threads
    float sum = g_gsum[g * 128 + c];
    float mx  = fdec(g_gmax[g * 128 + c]);
    float cnt = (float)(g_start[g + 1] - g_start[g]);
    sz[c]       = sum / fmaxf(cnt, 1.0f);
    sz[128 + c] = mx;
    sz[256 + c] = sum;
    __syncthreads();
    // Re-zero own-graph accumulators (only this block reads them).
    g_gsum[g * 128 + c] = 0.f;
    g_gmax[g * 128 + c] = 0u;
    // Re-zero histogram (not read by head; race-free across blocks).
    for (int i = g * 128 + c; i < N; i += G * 128) g_cnt[i] = 0;

    float acc = bf1[c];
    #pragma unroll 4
    for (int k = 0; k < 384; k++) acc += sz[k] * Wf1[k * 128 + c];
    sz2[c] = lrelu(acc);
    __syncthreads();
    if (c < 51) {
        float o = bf2[c];
        #pragma unroll 4
        for (int k = 0; k < 128; k++) o += sz2[k] * Wf2[k * 51 + c];
        out[g * 51 + c] = o;
    }
}

// ---------------------------------------------------------------------------
extern "C" void kernel_launch(void* const* d_in, const int* in_sizes, int n_in,
                              void* d_out, int out_size) {
    const float* x    = (const float*)d_in[0];
    const void*  eidx = d_in[1];
    const void*  batch= d_in[2];
    const float* W1l  = (const float*)d_in[3];
    const float* b1   = (const float*)d_in[4];
    const float* W1r  = (const float*)d_in[5];
    const float* W2l  = (const float*)d_in[6];
    const float* b2   = (const float*)d_in[7];
    const float* W2r  = (const float*)d_in[8];
    const float* W3l  = (const float*)d_in[9];
    const float* b3   = (const float*)d_in[10];
    const float* W3r  = (const float*)d_in[11];
    const float* Wu   = (const float*)d_in[12];
    const float* bu   = (const float*)d_in[13];
    const float* Wf1  = (const float*)d_in[14];
    const float* bf1  = (const float*)d_in[15];
    const float* Wf2  = (const float*)d_in[16];
    const float* bf2  = (const float*)d_in[17];
    float* out = (float*)d_out;

    int N = in_sizes[0];
    int E = in_sizes[1] / 2;
    int G = out_size / 51;
    int bbase = (N - 64) & ~1;

    int pairs = (N + 1) / 2;

    k_hist<<<(E + 255) / 256, 256>>>(eidx, E);
    k_scan1b<<<1, 1024>>>(N, E);
    k_csrfill<<<(E + 255) / 256, 256>>>(eidx, E);
    k_l1<<<(N + 7) / 8, 256>>>(x, W1l, b1, W1r, N);
    k_sage2<<<(pairs + 7) / 8, 256>>>(W2l, b2, W2r, N);
    k_sage3up_pool<<<(N + 255) / 256, 256>>>(W3l, b3, W3r, Wu, bu, batch, N, bbase);
    k_starts<<<(N + 255) / 256, 256>>>(batch, N, G, bbase);
    k_head<<<G, 128>>>(Wf1, bf1, Wf2, bf2, out, N, G);
}